// round 3
// baseline (speedup 1.0000x reference)
#include <cuda_runtime.h>

// ---------------------------------------------------------------------------
// TromptCell, B=C=P=D=256, fp32.
//   out[b,p,d] = (1+ew[p]) * sum_c mask[p,c]*x_emb[b,c,d] + mask[b,p]*eb[b]
// x_emb stored c-major ([C][B][D]) so the einsum is a single GEMM:
//   OUT[p, n] = sum_c mask[p,c] * XEMB[c, n],  n = b*256+d,  M=256,N=65536,K=256
// ---------------------------------------------------------------------------

#define D256 256
#define EPS_LN 1e-5f

static __device__ float g_xemb[256u * 256u * 256u];  // [c][b][d]
static __device__ float g_xprompt[256 * 256];        // [p][d]
static __device__ float g_xcol[256 * 256];           // [c][d]
static __device__ float g_mask[256 * 256];           // [p][c]

__device__ __forceinline__ float warpSum(float v) {
#pragma unroll
    for (int o = 16; o; o >>= 1) v += __shfl_xor_sync(0xffffffffu, v, o);
    return v;
}
__device__ __forceinline__ float warpMax(float v) {
#pragma unroll
    for (int o = 16; o; o >>= 1) v = fmaxf(v, __shfl_xor_sync(0xffffffffu, v, o));
    return v;
}

// 256-thread block reductions (8 warps). `red` must hold >= 8 floats.
__device__ __forceinline__ float blockSum256(float v, float* red) {
    float s = warpSum(v);
    if ((threadIdx.x & 31) == 0) red[threadIdx.x >> 5] = s;
    __syncthreads();
    float tot = red[0] + red[1] + red[2] + red[3] + red[4] + red[5] + red[6] + red[7];
    __syncthreads();
    return tot;
}
__device__ __forceinline__ float blockMax256(float v, float* red) {
    float s = warpMax(v);
    if ((threadIdx.x & 31) == 0) red[threadIdx.x >> 5] = s;
    __syncthreads();
    float m = fmaxf(fmaxf(fmaxf(red[0], red[1]), fmaxf(red[2], red[3])),
                    fmaxf(fmaxf(red[4], red[5]), fmaxf(red[6], red[7])));
    __syncthreads();
    return m;
}

// ---------------------------------------------------------------------------
// x_col = LN(emb_column).  One warp per row (8 rows / 256-thread block).
// ---------------------------------------------------------------------------
__global__ void ln_col_kernel(const float* __restrict__ in,
                              const float* __restrict__ w,
                              const float* __restrict__ bb) {
    int row  = blockIdx.x * 8 + (threadIdx.x >> 5);
    int lane = threadIdx.x & 31;
    const float4* ip = reinterpret_cast<const float4*>(in + row * D256);
    float4 v0 = ip[lane * 2], v1 = ip[lane * 2 + 1];
    float s = v0.x + v0.y + v0.z + v0.w + v1.x + v1.y + v1.z + v1.w;
    float mu = warpSum(s) * (1.0f / 256.0f);
    float q =
        (v0.x - mu) * (v0.x - mu) + (v0.y - mu) * (v0.y - mu) +
        (v0.z - mu) * (v0.z - mu) + (v0.w - mu) * (v0.w - mu) +
        (v1.x - mu) * (v1.x - mu) + (v1.y - mu) * (v1.y - mu) +
        (v1.z - mu) * (v1.z - mu) + (v1.w - mu) * (v1.w - mu);
    float rs = rsqrtf(warpSum(q) * (1.0f / 256.0f) + EPS_LN);
    const float4* wp = reinterpret_cast<const float4*>(w);
    const float4* bp = reinterpret_cast<const float4*>(bb);
    float4 w0 = wp[lane * 2], w1 = wp[lane * 2 + 1];
    float4 b0 = bp[lane * 2], b1 = bp[lane * 2 + 1];
    float4 o0, o1;
    o0.x = (v0.x - mu) * rs * w0.x + b0.x;  o0.y = (v0.y - mu) * rs * w0.y + b0.y;
    o0.z = (v0.z - mu) * rs * w0.z + b0.z;  o0.w = (v0.w - mu) * rs * w0.w + b0.w;
    o1.x = (v1.x - mu) * rs * w1.x + b1.x;  o1.y = (v1.y - mu) * rs * w1.y + b1.y;
    o1.z = (v1.z - mu) * rs * w1.z + b1.z;  o1.w = (v1.w - mu) * rs * w1.w + b1.w;
    float4* op = reinterpret_cast<float4*>(g_xcol + row * D256);
    op[lane * 2] = o0;
    op[lane * 2 + 1] = o1;
}

// ---------------------------------------------------------------------------
// x_emb[b,c,:] = LN(relu(fb[c,:] + x[b,c]*fw[c,:]))  -> g_xemb[c][b][:]
// One warp per (b,c) row; 8 rows per block.
// ---------------------------------------------------------------------------
__global__ void xemb_kernel(const float* __restrict__ x,
                            const float* __restrict__ fw,
                            const float* __restrict__ fb,
                            const float* __restrict__ w,
                            const float* __restrict__ bb) {
    int row  = blockIdx.x * 8 + (threadIdx.x >> 5);  // row = b*256 + c
    int lane = threadIdx.x & 31;
    int b = row >> 8, c = row & 255;
    float xv = __ldg(x + row);
    const float4* fwp = reinterpret_cast<const float4*>(fw + c * D256);
    const float4* fbp = reinterpret_cast<const float4*>(fb + c * D256);
    float4 a0 = fwp[lane * 2], a1 = fwp[lane * 2 + 1];
    float4 c0 = fbp[lane * 2], c1 = fbp[lane * 2 + 1];
    float4 v0, v1;
    v0.x = fmaxf(fmaf(xv, a0.x, c0.x), 0.f);  v0.y = fmaxf(fmaf(xv, a0.y, c0.y), 0.f);
    v0.z = fmaxf(fmaf(xv, a0.z, c0.z), 0.f);  v0.w = fmaxf(fmaf(xv, a0.w, c0.w), 0.f);
    v1.x = fmaxf(fmaf(xv, a1.x, c1.x), 0.f);  v1.y = fmaxf(fmaf(xv, a1.y, c1.y), 0.f);
    v1.z = fmaxf(fmaf(xv, a1.z, c1.z), 0.f);  v1.w = fmaxf(fmaf(xv, a1.w, c1.w), 0.f);
    float s = v0.x + v0.y + v0.z + v0.w + v1.x + v1.y + v1.z + v1.w;
    float mu = warpSum(s) * (1.0f / 256.0f);
    float q =
        (v0.x - mu) * (v0.x - mu) + (v0.y - mu) * (v0.y - mu) +
        (v0.z - mu) * (v0.z - mu) + (v0.w - mu) * (v0.w - mu) +
        (v1.x - mu) * (v1.x - mu) + (v1.y - mu) * (v1.y - mu) +
        (v1.z - mu) * (v1.z - mu) + (v1.w - mu) * (v1.w - mu);
    float rs = rsqrtf(warpSum(q) * (1.0f / 256.0f) + EPS_LN);
    const float4* wp = reinterpret_cast<const float4*>(w);
    const float4* bp = reinterpret_cast<const float4*>(bb);
    float4 w0 = wp[lane * 2], w1 = wp[lane * 2 + 1];
    float4 b0 = bp[lane * 2], b1 = bp[lane * 2 + 1];
    float4 o0, o1;
    o0.x = (v0.x - mu) * rs * w0.x + b0.x;  o0.y = (v0.y - mu) * rs * w0.y + b0.y;
    o0.z = (v0.z - mu) * rs * w0.z + b0.z;  o0.w = (v0.w - mu) * rs * w0.w + b0.w;
    o1.x = (v1.x - mu) * rs * w1.x + b1.x;  o1.y = (v1.y - mu) * rs * w1.y + b1.y;
    o1.z = (v1.z - mu) * rs * w1.z + b1.z;  o1.w = (v1.w - mu) * rs * w1.w + b1.w;
    float4* op = reinterpret_cast<float4*>(g_xemb + (size_t)c * 65536u + (size_t)b * 256u);
    op[lane * 2] = o0;
    op[lane * 2 + 1] = o1;
}

// ---------------------------------------------------------------------------
// x_prompt[p,:] = [LN(emb_prompt[p,:]) , prev[p,:]] @ W.T + dib + emb_prompt[p,:]
// One block per p; thread t owns output column d = t.
// ---------------------------------------------------------------------------
__global__ void xprompt_kernel(const float* __restrict__ emb_prompt,
                               const float* __restrict__ prev,
                               const float* __restrict__ lnw,
                               const float* __restrict__ lnb,
                               const float* __restrict__ W,     // [256, 512] row-major
                               const float* __restrict__ dib) {
    __shared__ float sh_in[512];
    __shared__ float red[8];
    int p = blockIdx.x, t = threadIdx.x;
    float e = emb_prompt[p * D256 + t];
    float mu = blockSum256(e, red) * (1.0f / 256.0f);
    float dlt = e - mu;
    float var = blockSum256(dlt * dlt, red) * (1.0f / 256.0f);
    float rs = rsqrtf(var + EPS_LN);
    sh_in[t]       = dlt * rs * lnw[t] + lnb[t];
    sh_in[256 + t] = prev[p * D256 + t];
    __syncthreads();
    float acc = dib[t] + e;
    const float4* wr = reinterpret_cast<const float4*>(W + t * 512);
    const float4* si = reinterpret_cast<const float4*>(sh_in);
#pragma unroll 8
    for (int k4 = 0; k4 < 128; k4++) {
        float4 wv = wr[k4];
        float4 sv = si[k4];
        acc = fmaf(wv.x, sv.x, acc);
        acc = fmaf(wv.y, sv.y, acc);
        acc = fmaf(wv.z, sv.z, acc);
        acc = fmaf(wv.w, sv.w, acc);
    }
    g_xprompt[p * D256 + t] = acc;
}

// ---------------------------------------------------------------------------
// mask[p,:] = softmax_c( x_prompt[p,:] . x_col[c,:] )
// One block per p; thread t owns column c = t.
// ---------------------------------------------------------------------------
__global__ void mask_kernel() {
    __shared__ float shxp[256];
    __shared__ float red[8];
    int p = blockIdx.x, t = threadIdx.x;
    shxp[t] = g_xprompt[p * D256 + t];
    __syncthreads();
    float acc = 0.f;
    const float4* xc = reinterpret_cast<const float4*>(g_xcol + t * D256);
    const float4* sp = reinterpret_cast<const float4*>(shxp);
#pragma unroll 8
    for (int k4 = 0; k4 < 64; k4++) {
        float4 a = xc[k4];
        float4 b = sp[k4];
        acc = fmaf(a.x, b.x, acc);
        acc = fmaf(a.y, b.y, acc);
        acc = fmaf(a.z, b.z, acc);
        acc = fmaf(a.w, b.w, acc);
    }
    float m = blockMax256(acc, red);
    float ex = __expf(acc - m);
    float s = blockSum256(ex, red);
    g_mask[p * D256 + t] = ex / s;
}

// ---------------------------------------------------------------------------
// OUT = mask[256x256] @ XEMB[256 x 65536] with fused epilogue.
// BM=128, BN=128, BK=16, 256 threads, 8x8 per thread.
// n = b*256 + d; BN=128 -> b is constant per block.
// out[b*65536 + m*256 + d] = acc*(1+ew[m]) + mask[b,m]*eb[b]
// ---------------------------------------------------------------------------
__global__ void __launch_bounds__(256) gemm_kernel(const float* __restrict__ ew,
                                                   const float* __restrict__ eb,
                                                   float* __restrict__ out) {
    __shared__ float As[16][128];  // As[k][m]
    __shared__ float Bs[16][128];  // Bs[k][n]
    int tid = threadIdx.x;
    int tx = tid & 15, ty = tid >> 4;
    int n0 = blockIdx.x * 128;
    int m0 = blockIdx.y * 128;
    int b = n0 >> 8;
    int dbase = n0 & 255;

    float acc[8][8];
#pragma unroll
    for (int i = 0; i < 8; i++)
#pragma unroll
        for (int j = 0; j < 8; j++) acc[i][j] = 0.f;

    const float* A = g_mask;
    const float* B = g_xemb;

    for (int k0 = 0; k0 < 256; k0 += 16) {
        // A tile: 128 rows x 16 cols -> As[k][m] (transposed store)
#pragma unroll
        for (int s = tid; s < 512; s += 256) {
            int row = s >> 2, c4 = s & 3;
            float4 v = *reinterpret_cast<const float4*>(A + (m0 + row) * 256 + k0 + c4 * 4);
            As[c4 * 4 + 0][row] = v.x;
            As[c4 * 4 + 1][row] = v.y;
            As[c4 * 4 + 2][row] = v.z;
            As[c4 * 4 + 3][row] = v.w;
        }
        // B tile: 16 rows x 128 cols, direct
#pragma unroll
        for (int s = tid; s < 512; s += 256) {
            int kr = s >> 5, n4 = s & 31;
            *reinterpret_cast<float4*>(&Bs[kr][n4 * 4]) =
                *reinterpret_cast<const float4*>(B + (size_t)(k0 + kr) * 65536u + n0 + n4 * 4);
        }
        __syncthreads();
#pragma unroll
        for (int kk = 0; kk < 16; kk++) {
            float ra[8], rb[8];
#pragma unroll
            for (int i = 0; i < 8; i++) ra[i] = As[kk][ty * 8 + i];
#pragma unroll
            for (int j = 0; j < 8; j++) rb[j] = Bs[kk][tx * 8 + j];
#pragma unroll
            for (int i = 0; i < 8; i++)
#pragma unroll
                for (int j = 0; j < 8; j++)
                    acc[i][j] = fmaf(ra[i], rb[j], acc[i][j]);
        }
        __syncthreads();
    }

    float ebb = __ldg(eb + b);
#pragma unroll
    for (int i = 0; i < 8; i++) {
        int m = m0 + ty * 8 + i;
        float scale = 1.0f + __ldg(ew + m);
        float bias = g_mask[b * 256 + m] * ebb;
        float* op = out + (size_t)b * 65536u + (size_t)m * 256u + dbase + tx * 8;
        float4 o0, o1;
        o0.x = fmaf(acc[i][0], scale, bias);
        o0.y = fmaf(acc[i][1], scale, bias);
        o0.z = fmaf(acc[i][2], scale, bias);
        o0.w = fmaf(acc[i][3], scale, bias);
        o1.x = fmaf(acc[i][4], scale, bias);
        o1.y = fmaf(acc[i][5], scale, bias);
        o1.z = fmaf(acc[i][6], scale, bias);
        o1.w = fmaf(acc[i][7], scale, bias);
        *reinterpret_cast<float4*>(op) = o0;
        *reinterpret_cast<float4*>(op + 4) = o1;
    }
}

// ---------------------------------------------------------------------------
extern "C" void kernel_launch(void* const* d_in, const int* in_sizes, int n_in,
                              void* d_out, int out_size) {
    (void)in_sizes; (void)n_in; (void)out_size;
    const float* x           = (const float*)d_in[0];   // [B,C]
    const float* prev        = (const float*)d_in[1];   // [P,D]
    const float* fw          = (const float*)d_in[2];   // [C,D]
    const float* fb          = (const float*)d_in[3];   // [1,C,D]
    const float* ln_emb_w    = (const float*)d_in[4];
    const float* ln_emb_b    = (const float*)d_in[5];
    const float* ln_col_w    = (const float*)d_in[6];
    const float* ln_col_b    = (const float*)d_in[7];
    const float* ln_prompt_w = (const float*)d_in[8];
    const float* ln_prompt_b = (const float*)d_in[9];
    const float* W           = (const float*)d_in[10];  // [D,2D]
    const float* dib         = (const float*)d_in[11];  // [D]
    const float* emb_column  = (const float*)d_in[12];  // [C,D]
    const float* emb_prompt  = (const float*)d_in[13];  // [P,D]
    const float* ew          = (const float*)d_in[14];  // [P,1]
    const float* eb          = (const float*)d_in[15];  // [P]
    float* out = (float*)d_out;                         // [1,B,P,D]

    ln_col_kernel<<<32, 256>>>(emb_column, ln_col_w, ln_col_b);
    xprompt_kernel<<<256, 256>>>(emb_prompt, prev, ln_prompt_w, ln_prompt_b, W, dib);
    mask_kernel<<<256, 256>>>();
    xemb_kernel<<<8192, 256>>>(x, fw, fb, ln_emb_w, ln_emb_b);
    gemm_kernel<<<dim3(512, 2), 256>>>(ew, eb, out);
}

// round 4
// speedup vs baseline: 1.0056x; 1.0056x over previous
#include <cuda_runtime.h>

// ---------------------------------------------------------------------------
// TromptCell, B=C=P=D=256, fp32.
//   out[b,p,d] = (1+ew[p]) * sum_c mask[p,c]*x_emb[b,c,d] + mask[b,p]*eb[b]
// x_emb stored c-major ([C][B][D]) so the einsum is a single GEMM:
//   OUT[p, n] = sum_c mask[p,c] * XEMB[c, n],  n = b*256+d,  M=256,N=65536,K=256
// ---------------------------------------------------------------------------

#define D256 256
#define EPS_LN 1e-5f

static __device__ float g_xemb[256u * 256u * 256u];  // [c][b][d]
static __device__ float g_xprompt[256 * 256];        // [p][d]
static __device__ float g_xcol[256 * 256];           // [c][d]
static __device__ float g_mask[256 * 256];           // [p][c]

__device__ __forceinline__ float warpSum(float v) {
#pragma unroll
    for (int o = 16; o; o >>= 1) v += __shfl_xor_sync(0xffffffffu, v, o);
    return v;
}
__device__ __forceinline__ float warpMax(float v) {
#pragma unroll
    for (int o = 16; o; o >>= 1) v = fmaxf(v, __shfl_xor_sync(0xffffffffu, v, o));
    return v;
}

// 256-thread block reductions (8 warps). `red` must hold >= 8 floats.
__device__ __forceinline__ float blockSum256(float v, float* red) {
    float s = warpSum(v);
    if ((threadIdx.x & 31) == 0) red[threadIdx.x >> 5] = s;
    __syncthreads();
    float tot = red[0] + red[1] + red[2] + red[3] + red[4] + red[5] + red[6] + red[7];
    __syncthreads();
    return tot;
}
__device__ __forceinline__ float blockMax256(float v, float* red) {
    float s = warpMax(v);
    if ((threadIdx.x & 31) == 0) red[threadIdx.x >> 5] = s;
    __syncthreads();
    float m = fmaxf(fmaxf(fmaxf(red[0], red[1]), fmaxf(red[2], red[3])),
                    fmaxf(fmaxf(red[4], red[5]), fmaxf(red[6], red[7])));
    __syncthreads();
    return m;
}

// ---------------------------------------------------------------------------
// x_col = LN(emb_column).  One warp per row (8 rows / 256-thread block).
// ---------------------------------------------------------------------------
__global__ void ln_col_kernel(const float* __restrict__ in,
                              const float* __restrict__ w,
                              const float* __restrict__ bb) {
    int row  = blockIdx.x * 8 + (threadIdx.x >> 5);
    int lane = threadIdx.x & 31;
    const float4* ip = reinterpret_cast<const float4*>(in + row * D256);
    float4 v0 = ip[lane * 2], v1 = ip[lane * 2 + 1];
    float s = v0.x + v0.y + v0.z + v0.w + v1.x + v1.y + v1.z + v1.w;
    float mu = warpSum(s) * (1.0f / 256.0f);
    float q =
        (v0.x - mu) * (v0.x - mu) + (v0.y - mu) * (v0.y - mu) +
        (v0.z - mu) * (v0.z - mu) + (v0.w - mu) * (v0.w - mu) +
        (v1.x - mu) * (v1.x - mu) + (v1.y - mu) * (v1.y - mu) +
        (v1.z - mu) * (v1.z - mu) + (v1.w - mu) * (v1.w - mu);
    float rs = rsqrtf(warpSum(q) * (1.0f / 256.0f) + EPS_LN);
    const float4* wp = reinterpret_cast<const float4*>(w);
    const float4* bp = reinterpret_cast<const float4*>(bb);
    float4 w0 = wp[lane * 2], w1 = wp[lane * 2 + 1];
    float4 b0 = bp[lane * 2], b1 = bp[lane * 2 + 1];
    float4 o0, o1;
    o0.x = (v0.x - mu) * rs * w0.x + b0.x;  o0.y = (v0.y - mu) * rs * w0.y + b0.y;
    o0.z = (v0.z - mu) * rs * w0.z + b0.z;  o0.w = (v0.w - mu) * rs * w0.w + b0.w;
    o1.x = (v1.x - mu) * rs * w1.x + b1.x;  o1.y = (v1.y - mu) * rs * w1.y + b1.y;
    o1.z = (v1.z - mu) * rs * w1.z + b1.z;  o1.w = (v1.w - mu) * rs * w1.w + b1.w;
    float4* op = reinterpret_cast<float4*>(g_xcol + row * D256);
    op[lane * 2] = o0;
    op[lane * 2 + 1] = o1;
}

// ---------------------------------------------------------------------------
// x_emb[b,c,:] = LN(relu(fb[c,:] + x[b,c]*fw[c,:]))  -> g_xemb[c][b][:]
// One warp per (b,c) row; 8 rows per block.
// ---------------------------------------------------------------------------
__global__ void xemb_kernel(const float* __restrict__ x,
                            const float* __restrict__ fw,
                            const float* __restrict__ fb,
                            const float* __restrict__ w,
                            const float* __restrict__ bb) {
    int row  = blockIdx.x * 8 + (threadIdx.x >> 5);  // row = b*256 + c
    int lane = threadIdx.x & 31;
    int b = row >> 8, c = row & 255;
    float xv = __ldg(x + row);
    const float4* fwp = reinterpret_cast<const float4*>(fw + c * D256);
    const float4* fbp = reinterpret_cast<const float4*>(fb + c * D256);
    float4 a0 = fwp[lane * 2], a1 = fwp[lane * 2 + 1];
    float4 c0 = fbp[lane * 2], c1 = fbp[lane * 2 + 1];
    float4 v0, v1;
    v0.x = fmaxf(fmaf(xv, a0.x, c0.x), 0.f);  v0.y = fmaxf(fmaf(xv, a0.y, c0.y), 0.f);
    v0.z = fmaxf(fmaf(xv, a0.z, c0.z), 0.f);  v0.w = fmaxf(fmaf(xv, a0.w, c0.w), 0.f);
    v1.x = fmaxf(fmaf(xv, a1.x, c1.x), 0.f);  v1.y = fmaxf(fmaf(xv, a1.y, c1.y), 0.f);
    v1.z = fmaxf(fmaf(xv, a1.z, c1.z), 0.f);  v1.w = fmaxf(fmaf(xv, a1.w, c1.w), 0.f);
    float s = v0.x + v0.y + v0.z + v0.w + v1.x + v1.y + v1.z + v1.w;
    float mu = warpSum(s) * (1.0f / 256.0f);
    float q =
        (v0.x - mu) * (v0.x - mu) + (v0.y - mu) * (v0.y - mu) +
        (v0.z - mu) * (v0.z - mu) + (v0.w - mu) * (v0.w - mu) +
        (v1.x - mu) * (v1.x - mu) + (v1.y - mu) * (v1.y - mu) +
        (v1.z - mu) * (v1.z - mu) + (v1.w - mu) * (v1.w - mu);
    float rs = rsqrtf(warpSum(q) * (1.0f / 256.0f) + EPS_LN);
    const float4* wp = reinterpret_cast<const float4*>(w);
    const float4* bp = reinterpret_cast<const float4*>(bb);
    float4 w0 = wp[lane * 2], w1 = wp[lane * 2 + 1];
    float4 b0 = bp[lane * 2], b1 = bp[lane * 2 + 1];
    float4 o0, o1;
    o0.x = (v0.x - mu) * rs * w0.x + b0.x;  o0.y = (v0.y - mu) * rs * w0.y + b0.y;
    o0.z = (v0.z - mu) * rs * w0.z + b0.z;  o0.w = (v0.w - mu) * rs * w0.w + b0.w;
    o1.x = (v1.x - mu) * rs * w1.x + b1.x;  o1.y = (v1.y - mu) * rs * w1.y + b1.y;
    o1.z = (v1.z - mu) * rs * w1.z + b1.z;  o1.w = (v1.w - mu) * rs * w1.w + b1.w;
    float4* op = reinterpret_cast<float4*>(g_xemb + (size_t)c * 65536u + (size_t)b * 256u);
    op[lane * 2] = o0;
    op[lane * 2 + 1] = o1;
}

// ---------------------------------------------------------------------------
// x_prompt[p,:] = [LN(emb_prompt[p,:]) , prev[p,:]] @ W.T + dib + emb_prompt[p,:]
// One block per p; thread t owns output column d = t.
// ---------------------------------------------------------------------------
__global__ void xprompt_kernel(const float* __restrict__ emb_prompt,
                               const float* __restrict__ prev,
                               const float* __restrict__ lnw,
                               const float* __restrict__ lnb,
                               const float* __restrict__ W,     // [256, 512] row-major
                               const float* __restrict__ dib) {
    __shared__ float sh_in[512];
    __shared__ float red[8];
    int p = blockIdx.x, t = threadIdx.x;
    float e = emb_prompt[p * D256 + t];
    float mu = blockSum256(e, red) * (1.0f / 256.0f);
    float dlt = e - mu;
    float var = blockSum256(dlt * dlt, red) * (1.0f / 256.0f);
    float rs = rsqrtf(var + EPS_LN);
    sh_in[t]       = dlt * rs * lnw[t] + lnb[t];
    sh_in[256 + t] = prev[p * D256 + t];
    __syncthreads();
    float acc = dib[t] + e;
    const float4* wr = reinterpret_cast<const float4*>(W + t * 512);
    const float4* si = reinterpret_cast<const float4*>(sh_in);
#pragma unroll 8
    for (int k4 = 0; k4 < 128; k4++) {
        float4 wv = wr[k4];
        float4 sv = si[k4];
        acc = fmaf(wv.x, sv.x, acc);
        acc = fmaf(wv.y, sv.y, acc);
        acc = fmaf(wv.z, sv.z, acc);
        acc = fmaf(wv.w, sv.w, acc);
    }
    g_xprompt[p * D256 + t] = acc;
}

// ---------------------------------------------------------------------------
// mask[p,:] = softmax_c( x_prompt[p,:] . x_col[c,:] )
// One block per p; thread t owns column c = t.
// ---------------------------------------------------------------------------
__global__ void mask_kernel() {
    __shared__ float shxp[256];
    __shared__ float red[8];
    int p = blockIdx.x, t = threadIdx.x;
    shxp[t] = g_xprompt[p * D256 + t];
    __syncthreads();
    float acc = 0.f;
    const float4* xc = reinterpret_cast<const float4*>(g_xcol + t * D256);
    const float4* sp = reinterpret_cast<const float4*>(shxp);
#pragma unroll 8
    for (int k4 = 0; k4 < 64; k4++) {
        float4 a = xc[k4];
        float4 b = sp[k4];
        acc = fmaf(a.x, b.x, acc);
        acc = fmaf(a.y, b.y, acc);
        acc = fmaf(a.z, b.z, acc);
        acc = fmaf(a.w, b.w, acc);
    }
    float m = blockMax256(acc, red);
    float ex = __expf(acc - m);
    float s = blockSum256(ex, red);
    g_mask[p * D256 + t] = ex / s;
}

// ---------------------------------------------------------------------------
// OUT = mask[256x256] @ XEMB[256 x 65536] with fused epilogue.
// BM=128, BN=128, BK=16, 256 threads, 8x8 per thread.
// n = b*256 + d; BN=128 -> b is constant per block.
// out[b*65536 + m*256 + d] = acc*(1+ew[m]) + mask[b,m]*eb[b]
// ---------------------------------------------------------------------------
__global__ void __launch_bounds__(256) gemm_kernel(const float* __restrict__ ew,
                                                   const float* __restrict__ eb,
                                                   float* __restrict__ out) {
    __shared__ float As[16][128];  // As[k][m]
    __shared__ float Bs[16][128];  // Bs[k][n]
    int tid = threadIdx.x;
    int tx = tid & 15, ty = tid >> 4;
    int n0 = blockIdx.x * 128;
    int m0 = blockIdx.y * 128;
    int b = n0 >> 8;
    int dbase = n0 & 255;

    float acc[8][8];
#pragma unroll
    for (int i = 0; i < 8; i++)
#pragma unroll
        for (int j = 0; j < 8; j++) acc[i][j] = 0.f;

    const float* A = g_mask;
    const float* B = g_xemb;

    for (int k0 = 0; k0 < 256; k0 += 16) {
        // A tile: 128 rows x 16 cols -> As[k][m] (transposed store)
#pragma unroll
        for (int s = tid; s < 512; s += 256) {
            int row = s >> 2, c4 = s & 3;
            float4 v = *reinterpret_cast<const float4*>(A + (m0 + row) * 256 + k0 + c4 * 4);
            As[c4 * 4 + 0][row] = v.x;
            As[c4 * 4 + 1][row] = v.y;
            As[c4 * 4 + 2][row] = v.z;
            As[c4 * 4 + 3][row] = v.w;
        }
        // B tile: 16 rows x 128 cols, direct
#pragma unroll
        for (int s = tid; s < 512; s += 256) {
            int kr = s >> 5, n4 = s & 31;
            *reinterpret_cast<float4*>(&Bs[kr][n4 * 4]) =
                *reinterpret_cast<const float4*>(B + (size_t)(k0 + kr) * 65536u + n0 + n4 * 4);
        }
        __syncthreads();
#pragma unroll
        for (int kk = 0; kk < 16; kk++) {
            float ra[8], rb[8];
#pragma unroll
            for (int i = 0; i < 8; i++) ra[i] = As[kk][ty * 8 + i];
#pragma unroll
            for (int j = 0; j < 8; j++) rb[j] = Bs[kk][tx * 8 + j];
#pragma unroll
            for (int i = 0; i < 8; i++)
#pragma unroll
                for (int j = 0; j < 8; j++)
                    acc[i][j] = fmaf(ra[i], rb[j], acc[i][j]);
        }
        __syncthreads();
    }

    float ebb = __ldg(eb + b);
#pragma unroll
    for (int i = 0; i < 8; i++) {
        int m = m0 + ty * 8 + i;
        float scale = 1.0f + __ldg(ew + m);
        float bias = g_mask[b * 256 + m] * ebb;
        float* op = out + (size_t)b * 65536u + (size_t)m * 256u + dbase + tx * 8;
        float4 o0, o1;
        o0.x = fmaf(acc[i][0], scale, bias);
        o0.y = fmaf(acc[i][1], scale, bias);
        o0.z = fmaf(acc[i][2], scale, bias);
        o0.w = fmaf(acc[i][3], scale, bias);
        o1.x = fmaf(acc[i][4], scale, bias);
        o1.y = fmaf(acc[i][5], scale, bias);
        o1.z = fmaf(acc[i][6], scale, bias);
        o1.w = fmaf(acc[i][7], scale, bias);
        *reinterpret_cast<float4*>(op) = o0;
        *reinterpret_cast<float4*>(op + 4) = o1;
    }
}

// ---------------------------------------------------------------------------
extern "C" void kernel_launch(void* const* d_in, const int* in_sizes, int n_in,
                              void* d_out, int out_size) {
    (void)in_sizes; (void)n_in; (void)out_size;
    const float* x           = (const float*)d_in[0];   // [B,C]
    const float* prev        = (const float*)d_in[1];   // [P,D]
    const float* fw          = (const float*)d_in[2];   // [C,D]
    const float* fb          = (const float*)d_in[3];   // [1,C,D]
    const float* ln_emb_w    = (const float*)d_in[4];
    const float* ln_emb_b    = (const float*)d_in[5];
    const float* ln_col_w    = (const float*)d_in[6];
    const float* ln_col_b    = (const float*)d_in[7];
    const float* ln_prompt_w = (const float*)d_in[8];
    const float* ln_prompt_b = (const float*)d_in[9];
    const float* W           = (const float*)d_in[10];  // [D,2D]
    const float* dib         = (const float*)d_in[11];  // [D]
    const float* emb_column  = (const float*)d_in[12];  // [C,D]
    const float* emb_prompt  = (const float*)d_in[13];  // [P,D]
    const float* ew          = (const float*)d_in[14];  // [P,1]
    const float* eb          = (const float*)d_in[15];  // [P]
    float* out = (float*)d_out;                         // [1,B,P,D]

    ln_col_kernel<<<32, 256>>>(emb_column, ln_col_w, ln_col_b);
    xprompt_kernel<<<256, 256>>>(emb_prompt, prev, ln_prompt_w, ln_prompt_b, W, dib);
    mask_kernel<<<256, 256>>>();
    xemb_kernel<<<8192, 256>>>(x, fw, fb, ln_emb_w, ln_emb_b);
    gemm_kernel<<<dim3(512, 2), 256>>>(ew, eb, out);
}